// round 10
// baseline (speedup 1.0000x reference)
#include <cuda_runtime.h>

#define C 256
#define H 8
#define NUM_DST 256
#define NMAX 50000
#define EMAX 300000
#define LISTCAP 8192
#define BCAP 4096         // smem-resident BFS edge cap (expected ~1536)
#define HB 512            // histogram/scatter blocks
#define INV_SQRT_DH 0.17677669529663687f
#define LOG2E 1.4426950408889634f
#define USCALE (INV_SQRT_DH * LOG2E)
#define LN_EPS 1e-5f
#define AW 4              // warps per attention block
#define AT (AW * 32)
#define SPLIT 4           // blocks per dst bucket
#define AGGSZ (NUM_DST * H * C)   // 524288

typedef unsigned long long u64;

__device__ int g_deg[NMAX];
__device__ int g_bcount[NUM_DST];
__device__ int g_bstart[NUM_DST];
__device__ int g_blockhist[HB * NUM_DST];
__device__ int g_blockbase[HB * NUM_DST];
__device__ int g_listcount;
__device__ int g_list[LISTCAP];
__device__ unsigned char g_spd[EMAX];
__device__ int g_sedge[EMAX];        // packed: src | (spd << 16), dst-bucket order
__device__ float g_u[NUM_DST * H * C];   // pre-scaled by 1/sqrt(DH)*log2(e)
__device__ float g_c0[NUM_DST * H];      // pre-scaled by 1/sqrt(DH)*log2(e)
__device__ float g_agg[AGGSZ];       // un-normalized per-dst per-head x aggregation
__device__ float g_l[NUM_DST * H];   // softmax denominators
__device__ float g_outsmall[NUM_DST * C];

// ---- f32x2 packed helpers --------------------------------------------------
__device__ __forceinline__ u64 pack2(float lo, float hi) {
    u64 r; asm("mov.b64 %0, {%1, %2};" : "=l"(r) : "f"(lo), "f"(hi)); return r;
}
__device__ __forceinline__ void unpack2(u64 v, float& lo, float& hi) {
    asm("mov.b64 {%0, %1}, %2;" : "=f"(lo), "=f"(hi) : "l"(v));
}
__device__ __forceinline__ void fma2(u64& d, u64 a, u64 b) {
    asm("fma.rn.f32x2 %0, %1, %2, %3;" : "=l"(d) : "l"(a), "l"(b), "l"(d));
}

// ---------------------------------------------------------------------------
// K0: init deg, list counter, agg/l accumulators
__global__ void k_init(int n) {
    int i = blockIdx.x * blockDim.x + threadIdx.x;
    if (i < n) g_deg[i] = 0;
    if (i < AGGSZ) g_agg[i] = 0.f;
    if (i < NUM_DST * H) g_l[i] = 0.f;
    if (i == 0) g_listcount = 0;
}

// ---------------------------------------------------------------------------
// K1: block-local histograms + out-degree + src<256 list
__global__ void k_hist(const int* __restrict__ src, const int* __restrict__ dst, int e) {
    __shared__ int hist[NUM_DST];
    int t = threadIdx.x;
    hist[t] = 0;
    __syncthreads();
    for (int i = blockIdx.x * blockDim.x + t; i < e; i += gridDim.x * blockDim.x) {
        int s = src[i], d = dst[i];
        atomicAdd(&g_deg[s], 1);
        atomicAdd(&hist[d], 1);
        if (s < NUM_DST) {
            int p = atomicAdd(&g_listcount, 1);
            if (p < LISTCAP) g_list[p] = i;
        }
    }
    __syncthreads();
    g_blockhist[blockIdx.x * NUM_DST + t] = hist[t];
}

// ---------------------------------------------------------------------------
// K2: fused single-block: (A) bucket prefix/bases + deg fold, (B) smem-CSR BFS
__global__ void k_prebfs(const int* __restrict__ src, const int* __restrict__ dst) {
    __shared__ int tmp[NUM_DST];
    __shared__ unsigned F0[NUM_DST][8];
    __shared__ unsigned F1[NUM_DST][8];
    __shared__ unsigned short epk[BCAP];
    __shared__ unsigned char esp[BCAP];
    __shared__ unsigned char csrc[BCAP];
    __shared__ int cnt[NUM_DST];
    __shared__ int scan[NUM_DST];
    __shared__ int cur[NUM_DST];
    int t = threadIdx.x;

    // ---- phase A: prefix over per-block histograms ----
    int total = 0;
    #pragma unroll 8
    for (int b = 0; b < HB; b++) total += g_blockhist[b * NUM_DST + t];
    tmp[t] = total;
    __syncthreads();
    for (int off = 1; off < NUM_DST; off <<= 1) {
        int v = (t >= off) ? tmp[t - off] : 0;
        __syncthreads();
        tmp[t] += v;
        __syncthreads();
    }
    int excl = tmp[t] - total;
    g_bstart[t] = excl;
    g_bcount[t] = total;
    g_deg[t] += total;  // in-degree (all dst < 256)
    int run = excl;
    for (int b = 0; b < HB; b++) {
        g_blockbase[b * NUM_DST + t] = run;
        run += g_blockhist[b * NUM_DST + t];
    }

    // ---- phase B: reverse-BFS (thread t owns frontier row t) ----
    #pragma unroll
    for (int w = 0; w < 8; w++)
        F0[t][w] = (w == (t >> 5)) ? (1u << (t & 31)) : 0u;
    cnt[t] = 0;
    __syncthreads();
    int lcnt = g_listcount;
    if (lcnt > LISTCAP) lcnt = LISTCAP;
    int scnt = lcnt < BCAP ? lcnt : BCAP;
    for (int i = t; i < scnt; i += 256) {
        int e = g_list[i];
        int s = src[e], d = dst[e];
        epk[i] = (unsigned short)(s | (d << 8));
        esp[i] = 4;
        atomicAdd(&cnt[d], 1);
    }
    for (int i = BCAP + t; i < lcnt; i += 256) g_spd[g_list[i]] = 4;
    __syncthreads();
    int myc = cnt[t];
    scan[t] = myc;
    __syncthreads();
    for (int off = 1; off < NUM_DST; off <<= 1) {
        int v = (t >= off) ? scan[t - off] : 0;
        __syncthreads();
        scan[t] += v;
        __syncthreads();
    }
    int base = scan[t] - myc;
    cur[t] = base;
    __syncthreads();
    for (int i = t; i < scnt; i += 256) {
        int p = epk[i];
        int d = p >> 8;
        int q = atomicAdd(&cur[d], 1);
        csrc[q] = (unsigned char)(p & 255);
    }
    __syncthreads();
    for (int k = 1; k <= 3; k++) {
        unsigned f0v = 0, f1v = 0, f2v = 0, f3v = 0, f4v = 0, f5v = 0, f6v = 0, f7v = 0;
        for (int j = base; j < base + myc; j++) {
            int s = csrc[j];
            f0v |= F0[s][0]; f1v |= F0[s][1]; f2v |= F0[s][2]; f3v |= F0[s][3];
            f4v |= F0[s][4]; f5v |= F0[s][5]; f6v |= F0[s][6]; f7v |= F0[s][7];
        }
        F1[t][0] = f0v; F1[t][1] = f1v; F1[t][2] = f2v; F1[t][3] = f3v;
        F1[t][4] = f4v; F1[t][5] = f5v; F1[t][6] = f6v; F1[t][7] = f7v;
        __syncthreads();
        for (int i = BCAP + t; i < lcnt; i += 256) {       // overflow path (unused)
            int e = g_list[i];
            int s = src[e], d = dst[e];
            #pragma unroll
            for (int w = 0; w < 8; w++) {
                unsigned v = F0[s][w];
                if (v) atomicOr(&F1[d][w], v);
            }
        }
        __syncthreads();
        for (int i = t; i < scnt; i += 256) {
            int p = epk[i];
            int s = p & 255, d = p >> 8;
            if (esp[i] == 4 && ((F1[s][d >> 5] >> (d & 31)) & 1u))
                esp[i] = (unsigned char)k;
        }
        for (int i = BCAP + t; i < lcnt; i += 256) {
            int e = g_list[i];
            int s = src[e], d = dst[e];
            if (g_spd[e] == 4 && ((F1[s][d >> 5] >> (d & 31)) & 1u))
                g_spd[e] = (unsigned char)k;
        }
        __syncthreads();
        #pragma unroll
        for (int w = 0; w < 8; w++) F0[t][w] = F1[t][w];
        __syncthreads();
    }
    for (int i = t; i < scnt; i += 256) g_spd[g_list[i]] = esp[i];
}

// ---------------------------------------------------------------------------
// K3: per-dst u/c0 precompute, pre-scaled by 1/sqrt(DH)*log2(e)
__global__ void k_qu(const float* __restrict__ x,
                     const float* __restrict__ Wq, const float* __restrict__ bq,
                     const float* __restrict__ Wk, const float* __restrict__ bk) {
    int d = blockIdx.x;
    int t = threadIdx.x, lane = t & 31, wp = t >> 5;
    __shared__ float xs[C], qs[C];
    xs[t] = x[d * C + t];
    __syncthreads();
    for (int j = wp; j < C; j += 8) {
        const float* wr = Wq + j * C;
        float p = 0.f;
        #pragma unroll
        for (int i = 0; i < 8; i++) p += wr[lane + 32 * i] * xs[lane + 32 * i];
        #pragma unroll
        for (int o = 16; o; o >>= 1) p += __shfl_xor_sync(0xffffffffu, p, o);
        if (lane == 0) qs[j] = p + bq[j];
    }
    __syncthreads();
    #pragma unroll
    for (int h = 0; h < H; h++) {
        float a0 = 0.f, a1 = 0.f, a2 = 0.f, a3 = 0.f;
        #pragma unroll
        for (int j = 0; j < 32; j += 4) {
            a0 += qs[h * 32 + j + 0] * Wk[(h * 32 + j + 0) * C + t];
            a1 += qs[h * 32 + j + 1] * Wk[(h * 32 + j + 1) * C + t];
            a2 += qs[h * 32 + j + 2] * Wk[(h * 32 + j + 2) * C + t];
            a3 += qs[h * 32 + j + 3] * Wk[(h * 32 + j + 3) * C + t];
        }
        g_u[d * H * C + h * C + t] = ((a0 + a1) + (a2 + a3)) * USCALE;
    }
    if (t < H) {
        float s = 0.f;
        #pragma unroll
        for (int j = 0; j < 32; j++) s += qs[t * 32 + j] * bk[t * 32 + j];
        g_c0[d * H + t] = s * USCALE;
    }
}

// ---------------------------------------------------------------------------
// K4: scatter with smem cursors; packs (src, spd) into one int
__global__ void k_scatter(const int* __restrict__ src, const int* __restrict__ dst, int e) {
    __shared__ int cur[NUM_DST];
    int t = threadIdx.x;
    cur[t] = g_blockbase[blockIdx.x * NUM_DST + t];
    __syncthreads();
    for (int i = blockIdx.x * blockDim.x + t; i < e; i += gridDim.x * blockDim.x) {
        int s = src[i], d = dst[i];
        int p = atomicAdd(&cur[d], 1);
        int sp = (s < NUM_DST) ? (int)g_spd[i] : 4;
        g_sedge[p] = s | (sp << 16);   // s < 50000 < 2^16
    }
}

// ---------------------------------------------------------------------------
// per-edge attention body (inlined twice per iteration for cross-edge ILP)
__device__ __forceinline__ void edge_body(
    int v, u64 xv0, u64 xv1, u64 xv2, u64 xv3,
    const u64 (&ur)[H][4], const float* csw,
    unsigned b4, unsigned b3, unsigned b2, int myh,
    u64 (&acc)[H][4], float& lsum)
{
    int sp = v >> 16;
    float p[H];
    #pragma unroll
    for (int h = 0; h < H; h++) {
        u64 q2 = 0ull;
        fma2(q2, xv0, ur[h][0]);
        fma2(q2, xv1, ur[h][1]);
        fma2(q2, xv2, ur[h][2]);
        fma2(q2, xv3, ur[h][3]);
        float lo, hi; unpack2(q2, lo, hi);
        p[h] = lo + hi;
    }
    float r4[4];
    #pragma unroll
    for (int j = 0; j < 4; j++) {
        float mine = b4 ? p[j + 4] : p[j];
        float send = b4 ? p[j] : p[j + 4];
        r4[j] = mine + __shfl_xor_sync(0xffffffffu, send, 16);
    }
    float r2[2];
    #pragma unroll
    for (int j = 0; j < 2; j++) {
        float mine = b3 ? r4[j + 2] : r4[j];
        float send = b3 ? r4[j] : r4[j + 2];
        r2[j] = mine + __shfl_xor_sync(0xffffffffu, send, 8);
    }
    float rr;
    {
        float mine = b2 ? r2[1] : r2[0];
        float send = b2 ? r2[0] : r2[1];
        rr = mine + __shfl_xor_sync(0xffffffffu, send, 4);
    }
    rr += __shfl_xor_sync(0xffffffffu, rr, 2);
    rr += __shfl_xor_sync(0xffffffffu, rr, 1);

    float wv = exp2f(rr + csw[sp * H + myh]);   // u/c0/spd_w pre-scaled by log2e
    lsum += wv;

    #pragma unroll
    for (int h = 0; h < H; h++) {
        float wh = __shfl_sync(0xffffffffu, wv, h * 4);
        u64 w2 = pack2(wh, wh);
        fma2(acc[h][0], w2, xv0);
        fma2(acc[h][1], w2, xv1);
        fma2(acc[h][2], w2, xv2);
        fma2(acc[h][3], w2, xv3);
    }
}

// ---------------------------------------------------------------------------
// K5: fused attention partials. SPLIT blocks per dst; 2 edges per iteration
// (independent chains -> ILP), u + acc in registers, prefetched pair loads.
__global__ __launch_bounds__(AT, 2)
void k_attn(const float* __restrict__ x, const float* __restrict__ spd_w) {
    int blk = blockIdx.x;
    int d = blk >> 2, seg = blk & 3;
    int t = threadIdx.x, lane = t & 31, wp = t >> 5;
    __shared__ __align__(16) float scratch[2][H * C];  // 16 KB
    __shared__ float csw[5 * H];
    __shared__ float lsh[AW * H];

    if (t < 40) csw[t] = g_c0[d * H + (t & 7)] + spd_w[t] * LOG2E;

    u64 ur[H][4];
    const float* ubase = g_u + d * (H * C) + lane * 8;
    #pragma unroll
    for (int h = 0; h < H; h++) {
        ulonglong2 p0 = *(const ulonglong2*)(ubase + h * C);
        ulonglong2 p1 = *(const ulonglong2*)(ubase + h * C + 4);
        ur[h][0] = p0.x; ur[h][1] = p0.y; ur[h][2] = p1.x; ur[h][3] = p1.y;
    }
    __syncthreads();

    int s0 = g_bstart[d], cnt = g_bcount[d];
    int b0 = s0 + (cnt * seg) / SPLIT;
    int b1 = s0 + (cnt * (seg + 1)) / SPLIT;

    int myh = (lane >> 2) & 7;
    unsigned b4 = (lane >> 4) & 1, b3 = (lane >> 3) & 1, b2 = (lane >> 2) & 1;

    u64 acc2[H][4];
    #pragma unroll
    for (int h = 0; h < H; h++)
        #pragma unroll
        for (int j = 0; j < 4; j++) acc2[h][j] = 0ull;
    float lsum = 0.f;

    // 2 edges per iteration, strided pairs, 1-pair-ahead prefetch
    int i = b0 + 2 * wp;
    int v0 = 0, v1 = 0;
    float4 A0, B0, A1, B1;
    if (i < b1) {
        v0 = g_sedge[i];
        const float4* r = (const float4*)(x + (v0 & 0xFFFF) * C) + lane * 2;
        A0 = r[0]; B0 = r[1];
    }
    if (i + 1 < b1) {
        v1 = g_sedge[i + 1];
        const float4* r = (const float4*)(x + (v1 & 0xFFFF) * C) + lane * 2;
        A1 = r[0]; B1 = r[1];
    }

    while (i < b1) {
        int ni = i + 2 * AW;
        int nv0 = 0, nv1 = 0;
        float4 nA0, nB0, nA1, nB1;
        if (ni < b1) {
            nv0 = g_sedge[ni];
            const float4* r = (const float4*)(x + (nv0 & 0xFFFF) * C) + lane * 2;
            nA0 = r[0]; nB0 = r[1];
        }
        if (ni + 1 < b1) {
            nv1 = g_sedge[ni + 1];
            const float4* r = (const float4*)(x + (nv1 & 0xFFFF) * C) + lane * 2;
            nA1 = r[0]; nB1 = r[1];
        }

        {
            u64 x0 = pack2(A0.x, A0.y), x1 = pack2(A0.z, A0.w);
            u64 x2 = pack2(B0.x, B0.y), x3 = pack2(B0.z, B0.w);
            edge_body(v0, x0, x1, x2, x3, ur, csw, b4, b3, b2, myh, acc2, lsum);
        }
        if (i + 1 < b1) {
            u64 x0 = pack2(A1.x, A1.y), x1 = pack2(A1.z, A1.w);
            u64 x2 = pack2(B1.x, B1.y), x3 = pack2(B1.z, B1.w);
            edge_body(v1, x0, x1, x2, x3, ur, csw, b4, b3, b2, myh, acc2, lsum);
        }

        v0 = nv0; v1 = nv1;
        A0 = nA0; B0 = nB0; A1 = nA1; B1 = nB1;
        i = ni;
    }

    // epilogue: warps 2,3 store; warps 0,1 add; then REDG combine to global
    if ((lane & 3) == 0) lsh[wp * H + myh] = lsum;
    if (wp >= 2) {
        #pragma unroll
        for (int h = 0; h < H; h++) {
            u64* dp = (u64*)&scratch[wp - 2][h * C + lane * 8];
            dp[0] = acc2[h][0]; dp[1] = acc2[h][1];
            dp[2] = acc2[h][2]; dp[3] = acc2[h][3];
        }
    }
    __syncthreads();
    if (wp < 2) {
        u64 one = pack2(1.f, 1.f);
        #pragma unroll
        for (int h = 0; h < H; h++) {
            u64* dp = (u64*)&scratch[wp][h * C + lane * 8];
            u64 s0q = dp[0], s1q = dp[1], s2q = dp[2], s3q = dp[3];
            fma2(s0q, one, acc2[h][0]);
            fma2(s1q, one, acc2[h][1]);
            fma2(s2q, one, acc2[h][2]);
            fma2(s3q, one, acc2[h][3]);
            dp[0] = s0q; dp[1] = s1q; dp[2] = s2q; dp[3] = s3q;
        }
    }
    __syncthreads();
    float* gbase = g_agg + d * (H * C);
    for (int idx = t; idx < H * C; idx += AT)
        atomicAdd(&gbase[idx], scratch[0][idx] + scratch[1][idx]);
    if (t < H) {
        float L = lsh[t] + lsh[H + t] + lsh[2 * H + t] + lsh[3 * H + t];
        atomicAdd(&g_l[d * H + t], L);
    }
}

// ---------------------------------------------------------------------------
// K6: normalize + V projection: out[c] = (agg[c/32]/L) . Wv[c,:] + bv[c]
__global__ void k_vproj(const float* __restrict__ Wv, const float* __restrict__ bv) {
    int d = blockIdx.x;
    int t = threadIdx.x, lane = t & 31, wp = t >> 5;
    __shared__ __align__(16) float agg[H * C];
    __shared__ float Linv[H];
    if (g_bcount[d] == 0) {
        g_outsmall[d * C + t] = 0.f;
        return;
    }
    if (t < H) Linv[t] = 1.f / g_l[d * H + t];
    __syncthreads();
    for (int idx = t; idx < H * C; idx += 256)
        agg[idx] = g_agg[d * (H * C) + idx] * Linv[idx >> 8];
    __syncthreads();
    for (int r = 0; r < 32; r++) {
        int c = wp * 32 + r;
        int h = c >> 5;
        const float4* wr = (const float4*)(Wv + c * C) + lane * 2;
        float4 wa = wr[0], wb = wr[1];
        const float* ar = &agg[h * C + lane * 8];
        float pacc = wa.x * ar[0] + wa.y * ar[1] + wa.z * ar[2] + wa.w * ar[3]
                   + wb.x * ar[4] + wb.y * ar[5] + wb.z * ar[6] + wb.w * ar[7];
        #pragma unroll
        for (int o = 16; o; o >>= 1) pacc += __shfl_xor_sync(0xffffffffu, pacc, o);
        if (lane == 0) g_outsmall[d * C + c] = pacc + bv[c];
    }
}

// ---------------------------------------------------------------------------
// K7: residual + degree + LayerNorm, one warp per row
__global__ void k_ln(const float* __restrict__ x,
                     const float* __restrict__ gamma, const float* __restrict__ beta,
                     float* __restrict__ out, int n) {
    int row = blockIdx.x * 8 + (threadIdx.x >> 5);
    int lane = threadIdx.x & 31;
    if (row >= n) return;
    const float* xr = x + (size_t)row * C + lane * 8;
    float4 a = *(const float4*)(xr);
    float4 b = *(const float4*)(xr + 4);
    float v[8] = {a.x, a.y, a.z, a.w, b.x, b.y, b.z, b.w};
    float degf = (float)g_deg[row];
    #pragma unroll
    for (int j = 0; j < 8; j++) v[j] += degf;
    if (row < NUM_DST) {
        const float* orow = g_outsmall + row * C + lane * 8;
        float4 oa = *(const float4*)(orow);
        float4 ob = *(const float4*)(orow + 4);
        v[0] += oa.x; v[1] += oa.y; v[2] += oa.z; v[3] += oa.w;
        v[4] += ob.x; v[5] += ob.y; v[6] += ob.z; v[7] += ob.w;
    }
    float s = 0.f;
    #pragma unroll
    for (int j = 0; j < 8; j++) s += v[j];
    #pragma unroll
    for (int o = 16; o; o >>= 1) s += __shfl_xor_sync(0xffffffffu, s, o);
    float mu = s * (1.f / C);
    float q = 0.f;
    #pragma unroll
    for (int j = 0; j < 8; j++) { float dd = v[j] - mu; q += dd * dd; }
    #pragma unroll
    for (int o = 16; o; o >>= 1) q += __shfl_xor_sync(0xffffffffu, q, o);
    float rstd = rsqrtf(q * (1.f / C) + LN_EPS);
    const float* gr = gamma + lane * 8;
    const float* br = beta + lane * 8;
    float4 g1 = *(const float4*)(gr);
    float4 g2 = *(const float4*)(gr + 4);
    float4 b1 = *(const float4*)(br);
    float4 b2 = *(const float4*)(br + 4);
    float gv[8] = {g1.x, g1.y, g1.z, g1.w, g2.x, g2.y, g2.z, g2.w};
    float bvv[8] = {b1.x, b1.y, b1.z, b1.w, b2.x, b2.y, b2.z, b2.w};
    float o[8];
    #pragma unroll
    for (int j = 0; j < 8; j++) o[j] = (v[j] - mu) * rstd * gv[j] + bvv[j];
    float* orow = out + (size_t)row * C + lane * 8;
    *(float4*)(orow) = make_float4(o[0], o[1], o[2], o[3]);
    *(float4*)(orow + 4) = make_float4(o[4], o[5], o[6], o[7]);
}

// ---------------------------------------------------------------------------
extern "C" void kernel_launch(void* const* d_in, const int* in_sizes, int n_in,
                              void* d_out, int out_size) {
    const float* x     = (const float*)d_in[0];
    const int*   src   = (const int*)d_in[1];
    const int*   dst   = (const int*)d_in[2];
    const float* Wq    = (const float*)d_in[3];
    const float* bq    = (const float*)d_in[4];
    const float* Wk    = (const float*)d_in[5];
    const float* bk    = (const float*)d_in[6];
    const float* Wv    = (const float*)d_in[7];
    const float* bv    = (const float*)d_in[8];
    const float* spd_w = (const float*)d_in[9];
    const float* gamma = (const float*)d_in[10];
    const float* beta  = (const float*)d_in[11];
    float* out = (float*)d_out;

    int n = in_sizes[0] / C;
    int e = in_sizes[1];
    int initN = (AGGSZ > n) ? AGGSZ : n;

    k_init<<<(initN + 255) / 256, 256>>>(n);
    k_hist<<<HB, 256>>>(src, dst, e);
    k_prebfs<<<1, 256>>>(src, dst);
    k_qu<<<NUM_DST, 256>>>(x, Wq, bq, Wk, bk);      // 4th launch -> ncu capture
    k_scatter<<<HB, 256>>>(src, dst, e);
    k_attn<<<NUM_DST * SPLIT, AT>>>(x, spd_w);
    k_vproj<<<NUM_DST, 256>>>(Wv, bv);
    k_ln<<<(n + 7) / 8, 256>>>(x, gamma, beta, out, n);
}

// round 12
// speedup vs baseline: 1.5114x; 1.5114x over previous
#include <cuda_runtime.h>

#define C 256
#define H 8
#define NUM_DST 256
#define NMAX 50000
#define EMAX 300000
#define LISTCAP 8192
#define BCAP 4096         // smem-resident BFS edge cap (expected ~1536)
#define HB 512            // histogram/scatter blocks
#define INV_SQRT_DH 0.17677669529663687f
#define LOG2E 1.4426950408889634f
#define USCALE (INV_SQRT_DH * LOG2E)
#define LN_EPS 1e-5f
#define AW 4              // warps per attention block
#define AT (AW * 32)
#define SPLIT 4           // blocks per dst bucket
#define AGGSZ (NUM_DST * H * C)   // 524288

typedef unsigned long long u64;

__device__ int g_deg[NMAX];
__device__ int g_bcount[NUM_DST];
__device__ int g_bstart[NUM_DST];
__device__ int g_blockhist[HB * NUM_DST];
__device__ int g_blockbase[HB * NUM_DST];
__device__ int g_listcount;
__device__ int g_list[LISTCAP];
__device__ unsigned char g_spd[EMAX];
__device__ int g_sedge[EMAX];        // packed: src | (spd << 16), dst-bucket order
__device__ float g_q[NUM_DST * C];       // Q = x@Wq^T + bq (dst rows only)
__device__ float g_u[NUM_DST * H * C];   // pre-scaled by 1/sqrt(DH)*log2(e)
__device__ float g_c0[NUM_DST * H];      // pre-scaled by 1/sqrt(DH)*log2(e)
__device__ float g_agg[AGGSZ];       // un-normalized per-dst per-head x aggregation
__device__ float g_l[NUM_DST * H];   // softmax denominators
__device__ float g_outsmall[NUM_DST * C];

// ---- f32x2 packed helpers --------------------------------------------------
__device__ __forceinline__ u64 pack2(float lo, float hi) {
    u64 r; asm("mov.b64 %0, {%1, %2};" : "=l"(r) : "f"(lo), "f"(hi)); return r;
}
__device__ __forceinline__ void unpack2(u64 v, float& lo, float& hi) {
    asm("mov.b64 {%0, %1}, %2;" : "=f"(lo), "=f"(hi) : "l"(v));
}
__device__ __forceinline__ void fma2(u64& d, u64 a, u64 b) {
    asm("fma.rn.f32x2 %0, %1, %2, %3;" : "=l"(d) : "l"(a), "l"(b), "l"(d));
}

// ---------------------------------------------------------------------------
// K0: init deg, list counter, agg/l accumulators
__global__ void k_init(int n) {
    int i = blockIdx.x * blockDim.x + threadIdx.x;
    if (i < n) g_deg[i] = 0;
    if (i < AGGSZ) g_agg[i] = 0.f;
    if (i < NUM_DST * H) g_l[i] = 0.f;
    if (i == 0) g_listcount = 0;
}

// ---------------------------------------------------------------------------
// K1: block-local histograms + out-degree + src<256 list
__global__ void k_hist(const int* __restrict__ src, const int* __restrict__ dst, int e) {
    __shared__ int hist[NUM_DST];
    int t = threadIdx.x;
    hist[t] = 0;
    __syncthreads();
    for (int i = blockIdx.x * blockDim.x + t; i < e; i += gridDim.x * blockDim.x) {
        int s = src[i], d = dst[i];
        atomicAdd(&g_deg[s], 1);
        atomicAdd(&hist[d], 1);
        if (s < NUM_DST) {
            int p = atomicAdd(&g_listcount, 1);
            if (p < LISTCAP) g_list[p] = i;
        }
    }
    __syncthreads();
    g_blockhist[blockIdx.x * NUM_DST + t] = hist[t];
}

// ---------------------------------------------------------------------------
// K2: fused single-block: (A) bucket prefix/bases + deg fold, (B) smem-CSR BFS
__global__ void k_prebfs(const int* __restrict__ src, const int* __restrict__ dst) {
    __shared__ int tmp[NUM_DST];
    __shared__ unsigned F0[NUM_DST][8];
    __shared__ unsigned F1[NUM_DST][8];
    __shared__ unsigned short epk[BCAP];
    __shared__ unsigned char esp[BCAP];
    __shared__ unsigned char csrc[BCAP];
    __shared__ int cnt[NUM_DST];
    __shared__ int scan[NUM_DST];
    __shared__ int cur[NUM_DST];
    int t = threadIdx.x;

    // ---- phase A: prefix over per-block histograms ----
    int total = 0;
    #pragma unroll 8
    for (int b = 0; b < HB; b++) total += g_blockhist[b * NUM_DST + t];
    tmp[t] = total;
    __syncthreads();
    for (int off = 1; off < NUM_DST; off <<= 1) {
        int v = (t >= off) ? tmp[t - off] : 0;
        __syncthreads();
        tmp[t] += v;
        __syncthreads();
    }
    int excl = tmp[t] - total;
    g_bstart[t] = excl;
    g_bcount[t] = total;
    g_deg[t] += total;  // in-degree (all dst < 256)
    int run = excl;
    for (int b = 0; b < HB; b++) {
        g_blockbase[b * NUM_DST + t] = run;
        run += g_blockhist[b * NUM_DST + t];
    }

    // ---- phase B: reverse-BFS (thread t owns frontier row t) ----
    #pragma unroll
    for (int w = 0; w < 8; w++)
        F0[t][w] = (w == (t >> 5)) ? (1u << (t & 31)) : 0u;
    cnt[t] = 0;
    __syncthreads();
    int lcnt = g_listcount;
    if (lcnt > LISTCAP) lcnt = LISTCAP;
    int scnt = lcnt < BCAP ? lcnt : BCAP;
    for (int i = t; i < scnt; i += 256) {
        int e = g_list[i];
        int s = src[e], d = dst[e];
        epk[i] = (unsigned short)(s | (d << 8));
        esp[i] = 4;
        atomicAdd(&cnt[d], 1);
    }
    for (int i = BCAP + t; i < lcnt; i += 256) g_spd[g_list[i]] = 4;
    __syncthreads();
    int myc = cnt[t];
    scan[t] = myc;
    __syncthreads();
    for (int off = 1; off < NUM_DST; off <<= 1) {
        int v = (t >= off) ? scan[t - off] : 0;
        __syncthreads();
        scan[t] += v;
        __syncthreads();
    }
    int base = scan[t] - myc;
    cur[t] = base;
    __syncthreads();
    for (int i = t; i < scnt; i += 256) {
        int p = epk[i];
        int d = p >> 8;
        int q = atomicAdd(&cur[d], 1);
        csrc[q] = (unsigned char)(p & 255);
    }
    __syncthreads();
    for (int k = 1; k <= 3; k++) {
        unsigned f0v = 0, f1v = 0, f2v = 0, f3v = 0, f4v = 0, f5v = 0, f6v = 0, f7v = 0;
        for (int j = base; j < base + myc; j++) {
            int s = csrc[j];
            f0v |= F0[s][0]; f1v |= F0[s][1]; f2v |= F0[s][2]; f3v |= F0[s][3];
            f4v |= F0[s][4]; f5v |= F0[s][5]; f6v |= F0[s][6]; f7v |= F0[s][7];
        }
        F1[t][0] = f0v; F1[t][1] = f1v; F1[t][2] = f2v; F1[t][3] = f3v;
        F1[t][4] = f4v; F1[t][5] = f5v; F1[t][6] = f6v; F1[t][7] = f7v;
        __syncthreads();
        for (int i = BCAP + t; i < lcnt; i += 256) {       // overflow path (unused)
            int e = g_list[i];
            int s = src[e], d = dst[e];
            #pragma unroll
            for (int w = 0; w < 8; w++) {
                unsigned v = F0[s][w];
                if (v) atomicOr(&F1[d][w], v);
            }
        }
        __syncthreads();
        for (int i = t; i < scnt; i += 256) {
            int p = epk[i];
            int s = p & 255, d = p >> 8;
            if (esp[i] == 4 && ((F1[s][d >> 5] >> (d & 31)) & 1u))
                esp[i] = (unsigned char)k;
        }
        for (int i = BCAP + t; i < lcnt; i += 256) {
            int e = g_list[i];
            int s = src[e], d = dst[e];
            if (g_spd[e] == 4 && ((F1[s][d >> 5] >> (d & 31)) & 1u))
                g_spd[e] = (unsigned char)k;
        }
        __syncthreads();
        #pragma unroll
        for (int w = 0; w < 8; w++) F0[t][w] = F1[t][w];
        __syncthreads();
    }
    for (int i = t; i < scnt; i += 256) g_spd[g_list[i]] = esp[i];
}

// ---------------------------------------------------------------------------
// K3a: Q = x[0:256] @ Wq^T + bq  (tiled GEMM, 64x64 tiles, 4x4 microtiles)
__global__ void k_q(const float* __restrict__ x,
                    const float* __restrict__ Wq, const float* __restrict__ bq) {
    __shared__ float Xs[64][33];
    __shared__ float Ws[64][33];
    int t = threadIdx.x;
    int tx = t & 15, ty = t >> 4;
    int bm = blockIdx.y * 64, bn = blockIdx.x * 64;
    float acc[4][4];
    #pragma unroll
    for (int i = 0; i < 4; i++)
        #pragma unroll
        for (int j = 0; j < 4; j++) acc[i][j] = 0.f;

    for (int k0 = 0; k0 < C; k0 += 32) {
        #pragma unroll
        for (int l = 0; l < 8; l++) {
            int idx = t + l * 256;
            int r = idx >> 5, c = idx & 31;
            Xs[r][c] = x[(bm + r) * C + k0 + c];
            Ws[r][c] = Wq[(bn + r) * C + k0 + c];
        }
        __syncthreads();
        #pragma unroll
        for (int kk = 0; kk < 32; kk++) {
            float av[4], bv[4];
            #pragma unroll
            for (int i = 0; i < 4; i++) av[i] = Xs[ty * 4 + i][kk];
            #pragma unroll
            for (int j = 0; j < 4; j++) bv[j] = Ws[tx * 4 + j][kk];
            #pragma unroll
            for (int i = 0; i < 4; i++)
                #pragma unroll
                for (int j = 0; j < 4; j++) acc[i][j] += av[i] * bv[j];
        }
        __syncthreads();
    }
    #pragma unroll
    for (int i = 0; i < 4; i++)
        #pragma unroll
        for (int j = 0; j < 4; j++)
            g_q[(bm + ty * 4 + i) * C + bn + tx * 4 + j] = acc[i][j] + bq[bn + tx * 4 + j];
}

// ---------------------------------------------------------------------------
// K3b: u[d][h][k] = (sum_j Q[d][h*32+j] * Wk[h*32+j][k]) * USCALE
// Per-head GEMM M=64-tile, N=64-tile, K=32. grid (4 ktiles, 4 dtiles, 8 heads)
__global__ void k_u(const float* __restrict__ Wk) {
    __shared__ float Qs[64][33];
    __shared__ float Ws[32][64];
    int t = threadIdx.x;
    int tx = t & 15, ty = t >> 4;
    int kx = blockIdx.x * 64, dy = blockIdx.y * 64, h = blockIdx.z;
    // load Q tile [64 dst][32 j]
    #pragma unroll
    for (int l = 0; l < 8; l++) {
        int idx = t + l * 256;
        int r = idx >> 5, c = idx & 31;
        Qs[r][c] = g_q[(dy + r) * C + h * 32 + c];
    }
    // load Wk tile [32 j][64 k]
    #pragma unroll
    for (int l = 0; l < 8; l++) {
        int idx = t + l * 256;
        int r = idx >> 6, c = idx & 63;
        Ws[r][c] = Wk[(h * 32 + r) * C + kx + c];
    }
    __syncthreads();
    float acc[4][4];
    #pragma unroll
    for (int i = 0; i < 4; i++)
        #pragma unroll
        for (int j = 0; j < 4; j++) acc[i][j] = 0.f;
    #pragma unroll
    for (int kk = 0; kk < 32; kk++) {
        float av[4], bv[4];
        #pragma unroll
        for (int i = 0; i < 4; i++) av[i] = Qs[ty * 4 + i][kk];
        #pragma unroll
        for (int j = 0; j < 4; j++) bv[j] = Ws[kk][tx * 4 + j];
        #pragma unroll
        for (int i = 0; i < 4; i++)
            #pragma unroll
            for (int j = 0; j < 4; j++) acc[i][j] += av[i] * bv[j];
    }
    #pragma unroll
    for (int i = 0; i < 4; i++)
        #pragma unroll
        for (int j = 0; j < 4; j++)
            g_u[(dy + ty * 4 + i) * (H * C) + h * C + kx + tx * 4 + j] = acc[i][j] * USCALE;
}

// ---------------------------------------------------------------------------
// K3c: c0[d][h] = (sum_j Q[d][h*32+j] * bk[h*32+j]) * USCALE
__global__ void k_c0(const float* __restrict__ bk) {
    __shared__ float bks[32];
    int h = blockIdx.x, d = threadIdx.x;
    if (d < 32) bks[d] = bk[h * 32 + d];
    __syncthreads();
    float s = 0.f;
    #pragma unroll
    for (int j = 0; j < 32; j++) s += g_q[d * C + h * 32 + j] * bks[j];
    g_c0[d * H + h] = s * USCALE;
}

// ---------------------------------------------------------------------------
// K4: scatter with smem cursors; packs (src, spd) into one int
__global__ void k_scatter(const int* __restrict__ src, const int* __restrict__ dst, int e) {
    __shared__ int cur[NUM_DST];
    int t = threadIdx.x;
    cur[t] = g_blockbase[blockIdx.x * NUM_DST + t];
    __syncthreads();
    for (int i = blockIdx.x * blockDim.x + t; i < e; i += gridDim.x * blockDim.x) {
        int s = src[i], d = dst[i];
        int p = atomicAdd(&cur[d], 1);
        int sp = (s < NUM_DST) ? (int)g_spd[i] : 4;
        g_sedge[p] = s | (sp << 16);   // s < 50000 < 2^16
    }
}

// ---------------------------------------------------------------------------
// K5: fused attention partials. SPLIT blocks per dst; u + acc in registers,
// single-edge software pipeline (R9 configuration), f32x2 packed FMAs.
__global__ __launch_bounds__(AT, 2)
void k_attn(const float* __restrict__ x, const float* __restrict__ spd_w) {
    int blk = blockIdx.x;
    int d = blk >> 2, seg = blk & 3;
    int t = threadIdx.x, lane = t & 31, wp = t >> 5;
    __shared__ __align__(16) float scratch[2][H * C];  // 16 KB
    __shared__ float csw[5 * H];
    __shared__ float lsh[AW * H];

    if (t < 40) csw[t] = g_c0[d * H + (t & 7)] + spd_w[t] * LOG2E;

    u64 ur[H][4];
    const float* ubase = g_u + d * (H * C) + lane * 8;
    #pragma unroll
    for (int h = 0; h < H; h++) {
        ulonglong2 p0 = *(const ulonglong2*)(ubase + h * C);
        ulonglong2 p1 = *(const ulonglong2*)(ubase + h * C + 4);
        ur[h][0] = p0.x; ur[h][1] = p0.y; ur[h][2] = p1.x; ur[h][3] = p1.y;
    }
    __syncthreads();

    int s0 = g_bstart[d], cnt = g_bcount[d];
    int b0 = s0 + (cnt * seg) / SPLIT;
    int b1 = s0 + (cnt * (seg + 1)) / SPLIT;

    int myh = (lane >> 2) & 7;
    unsigned b4 = (lane >> 4) & 1, b3 = (lane >> 3) & 1, b2 = (lane >> 2) & 1;

    u64 acc2[H][4];
    #pragma unroll
    for (int h = 0; h < H; h++)
        #pragma unroll
        for (int j = 0; j < 4; j++) acc2[h][j] = 0ull;
    float lsum = 0.f;

    // software pipeline: edge record + x row prefetched one iteration ahead
    int i = b0 + wp;
    int v0 = (i < b1) ? g_sedge[i] : 0;
    const float4* xr0 = (const float4*)(x + (v0 & 0xFFFF) * C) + lane * 2;
    float4 a, b;
    if (i < b1) { a = xr0[0]; b = xr0[1]; }

    for (; i < b1; i += AW) {
        int v1 = ((i + AW) < b1) ? g_sedge[i + AW] : 0;
        const float4* xr1 = (const float4*)(x + (v1 & 0xFFFF) * C) + lane * 2;
        float4 na, nb;
        if (i + AW < b1) { na = xr1[0]; nb = xr1[1]; }
        int sp = v0 >> 16;

        u64 xv2[4];
        xv2[0] = pack2(a.x, a.y); xv2[1] = pack2(a.z, a.w);
        xv2[2] = pack2(b.x, b.y); xv2[3] = pack2(b.z, b.w);

        float p[H];
        #pragma unroll
        for (int h = 0; h < H; h++) {
            u64 q2 = 0ull;
            fma2(q2, xv2[0], ur[h][0]);
            fma2(q2, xv2[1], ur[h][1]);
            fma2(q2, xv2[2], ur[h][2]);
            fma2(q2, xv2[3], ur[h][3]);
            float lo, hi; unpack2(q2, lo, hi);
            p[h] = lo + hi;
        }

        // head-folding butterfly: 9 shfls total
        float r4[4];
        #pragma unroll
        for (int j = 0; j < 4; j++) {
            float mine = b4 ? p[j + 4] : p[j];
            float send = b4 ? p[j] : p[j + 4];
            r4[j] = mine + __shfl_xor_sync(0xffffffffu, send, 16);
        }
        float r2[2];
        #pragma unroll
        for (int j = 0; j < 2; j++) {
            float mine = b3 ? r4[j + 2] : r4[j];
            float send = b3 ? r4[j] : r4[j + 2];
            r2[j] = mine + __shfl_xor_sync(0xffffffffu, send, 8);
        }
        {
            float mine = b2 ? r2[1] : r2[0];
            float send = b2 ? r2[0] : r2[1];
            r2[0] = mine + __shfl_xor_sync(0xffffffffu, send, 4);
        }
        r2[0] += __shfl_xor_sync(0xffffffffu, r2[0], 2);
        r2[0] += __shfl_xor_sync(0xffffffffu, r2[0], 1);

        float wv = exp2f(r2[0] + csw[sp * H + myh]);   // pre-scaled by log2e
        lsum += wv;

        #pragma unroll
        for (int h = 0; h < H; h++) {
            float wh = __shfl_sync(0xffffffffu, wv, h * 4);
            u64 w2 = pack2(wh, wh);
            fma2(acc2[h][0], w2, xv2[0]);
            fma2(acc2[h][1], w2, xv2[1]);
            fma2(acc2[h][2], w2, xv2[2]);
            fma2(acc2[h][3], w2, xv2[3]);
        }

        v0 = v1; a = na; b = nb;
    }

    // epilogue: warps 2,3 store; warps 0,1 add; then REDG combine to global
    if ((lane & 3) == 0) lsh[wp * H + myh] = lsum;
    if (wp >= 2) {
        #pragma unroll
        for (int h = 0; h < H; h++) {
            u64* dp = (u64*)&scratch[wp - 2][h * C + lane * 8];
            dp[0] = acc2[h][0]; dp[1] = acc2[h][1];
            dp[2] = acc2[h][2]; dp[3] = acc2[h][3];
        }
    }
    __syncthreads();
    if (wp < 2) {
        u64 one = pack2(1.f, 1.f);
        #pragma unroll
        for (int h = 0; h < H; h++) {
            u64* dp = (u64*)&scratch[wp][h * C + lane * 8];
            u64 s0q = dp[0], s1q = dp[1], s2q = dp[2], s3q = dp[3];
            fma2(s0q, one, acc2[h][0]);
            fma2(s1q, one, acc2[h][1]);
            fma2(s2q, one, acc2[h][2]);
            fma2(s3q, one, acc2[h][3]);
            dp[0] = s0q; dp[1] = s1q; dp[2] = s2q; dp[3] = s3q;
        }
    }
    __syncthreads();
    float* gbase = g_agg + d * (H * C);
    for (int idx = t; idx < H * C; idx += AT)
        atomicAdd(&gbase[idx], scratch[0][idx] + scratch[1][idx]);
    if (t < H) {
        float L = lsh[t] + lsh[H + t] + lsh[2 * H + t] + lsh[3 * H + t];
        atomicAdd(&g_l[d * H + t], L);
    }
}

// ---------------------------------------------------------------------------
// K6: normalize + V projection: out[c] = (agg[c/32]/L) . Wv[c,:] + bv[c]
__global__ void k_vproj(const float* __restrict__ Wv, const float* __restrict__ bv) {
    int d = blockIdx.x;
    int t = threadIdx.x, lane = t & 31, wp = t >> 5;
    __shared__ __align__(16) float agg[H * C];
    __shared__ float Linv[H];
    if (g_bcount[d] == 0) {
        g_outsmall[d * C + t] = 0.f;
        return;
    }
    if (t < H) Linv[t] = 1.f / g_l[d * H + t];
    __syncthreads();
    for (int idx = t; idx < H * C; idx += 256)
        agg[idx] = g_agg[d * (H * C) + idx] * Linv[idx >> 8];
    __syncthreads();
    for (int r = 0; r < 32; r++) {
        int c = wp * 32 + r;
        int h = c >> 5;
        const float4* wr = (const float4*)(Wv + c * C) + lane * 2;
        float4 wa = wr[0], wb = wr[1];
        const float* ar = &agg[h * C + lane * 8];
        float pacc = wa.x * ar[0] + wa.y * ar[1] + wa.z * ar[2] + wa.w * ar[3]
                   + wb.x * ar[4] + wb.y * ar[5] + wb.z * ar[6] + wb.w * ar[7];
        #pragma unroll
        for (int o = 16; o; o >>= 1) pacc += __shfl_xor_sync(0xffffffffu, pacc, o);
        if (lane == 0) g_outsmall[d * C + c] = pacc + bv[c];
    }
}

// ---------------------------------------------------------------------------
// K7: residual + degree + LayerNorm, one warp per row
__global__ void k_ln(const float* __restrict__ x,
                     const float* __restrict__ gamma, const float* __restrict__ beta,
                     float* __restrict__ out, int n) {
    int row = blockIdx.x * 8 + (threadIdx.x >> 5);
    int lane = threadIdx.x & 31;
    if (row >= n) return;
    const float* xr = x + (size_t)row * C + lane * 8;
    float4 a = *(const float4*)(xr);
    float4 b = *(const float4*)(xr + 4);
    float v[8] = {a.x, a.y, a.z, a.w, b.x, b.y, b.z, b.w};
    float degf = (float)g_deg[row];
    #pragma unroll
    for (int j = 0; j < 8; j++) v[j] += degf;
    if (row < NUM_DST) {
        const float* orow = g_outsmall + row * C + lane * 8;
        float4 oa = *(const float4*)(orow);
        float4 ob = *(const float4*)(orow + 4);
        v[0] += oa.x; v[1] += oa.y; v[2] += oa.z; v[3] += oa.w;
        v[4] += ob.x; v[5] += ob.y; v[6] += ob.z; v[7] += ob.w;
    }
    float s = 0.f;
    #pragma unroll
    for (int j = 0; j < 8; j++) s += v[j];
    #pragma unroll
    for (int o = 16; o; o >>= 1) s += __shfl_xor_sync(0xffffffffu, s, o);
    float mu = s * (1.f / C);
    float q = 0.f;
    #pragma unroll
    for (int j = 0; j < 8; j++) { float dd = v[j] - mu; q += dd * dd; }
    #pragma unroll
    for (int o = 16; o; o >>= 1) q += __shfl_xor_sync(0xffffffffu, q, o);
    float rstd = rsqrtf(q * (1.f / C) + LN_EPS);
    const float* gr = gamma + lane * 8;
    const float* br = beta + lane * 8;
    float4 g1 = *(const float4*)(gr);
    float4 g2 = *(const float4*)(gr + 4);
    float4 b1 = *(const float4*)(br);
    float4 b2 = *(const float4*)(br + 4);
    float gv[8] = {g1.x, g1.y, g1.z, g1.w, g2.x, g2.y, g2.z, g2.w};
    float bvv[8] = {b1.x, b1.y, b1.z, b1.w, b2.x, b2.y, b2.z, b2.w};
    float o[8];
    #pragma unroll
    for (int j = 0; j < 8; j++) o[j] = (v[j] - mu) * rstd * gv[j] + bvv[j];
    float* orow = out + (size_t)row * C + lane * 8;
    *(float4*)(orow) = make_float4(o[0], o[1], o[2], o[3]);
    *(float4*)(orow + 4) = make_float4(o[4], o[5], o[6], o[7]);
}

// ---------------------------------------------------------------------------
extern "C" void kernel_launch(void* const* d_in, const int* in_sizes, int n_in,
                              void* d_out, int out_size) {
    const float* x     = (const float*)d_in[0];
    const int*   src   = (const int*)d_in[1];
    const int*   dst   = (const int*)d_in[2];
    const float* Wq    = (const float*)d_in[3];
    const float* bq    = (const float*)d_in[4];
    const float* Wk    = (const float*)d_in[5];
    const float* bk    = (const float*)d_in[6];
    const float* Wv    = (const float*)d_in[7];
    const float* bv    = (const float*)d_in[8];
    const float* spd_w = (const float*)d_in[9];
    const float* gamma = (const float*)d_in[10];
    const float* beta  = (const float*)d_in[11];
    float* out = (float*)d_out;

    int n = in_sizes[0] / C;
    int e = in_sizes[1];
    int initN = (AGGSZ > n) ? AGGSZ : n;

    k_init<<<(initN + 255) / 256, 256>>>(n);
    k_hist<<<HB, 256>>>(src, dst, e);
    k_prebfs<<<1, 256>>>(src, dst);
    k_q<<<dim3(4, 4), 256>>>(x, Wq, bq);           // 4th launch -> ncu capture
    k_u<<<dim3(4, 4, 8), 256>>>(Wk);
    k_c0<<<H, 256>>>(bk);
    k_scatter<<<HB, 256>>>(src, dst, e);
    k_attn<<<NUM_DST * SPLIT, AT>>>(x, spd_w);
    k_vproj<<<NUM_DST, 256>>>(Wv, bv);
    k_ln<<<(n + 7) / 8, 256>>>(x, gamma, beta, out, n);
}